// round 13
// baseline (speedup 1.0000x reference)
#include <cuda_runtime.h>
#include <cstdint>
#include <math.h>

// YOLO loss over [16384, 7, 7, 14] fp32 (~90 MB read, scalar out).
// R13: 4-buffer bulk-TMA ring, prefetch 3 stages ahead (vs 1 in R11/R12)
// to close the convoy gaps that left DRAM at 61%. 128 cells/stage,
// 128 threads/CTA, 57 KB smem -> 4 CTAs/SM, grid 592.

#define THREADS        128
#define CELLS_PER_STG  128
#define STG_ONE        7168                      // 128 cells * 56 B
#define STG_BYTES      (2 * STG_ONE)             // 14336 (pred+tgt)
#define NBUF           4
#define SMEM_DATA_OFF  128                       // mbarriers live below
#define SMEM_BYTES     (SMEM_DATA_OFF + NBUF * STG_BYTES)   // 57472 B
#define MAX_BLOCKS     8192

__device__ float        g_partials[MAX_BLOCKS];
__device__ unsigned int g_count = 0;

static __device__ __forceinline__ void mbar_init(uint32_t mbar, uint32_t cnt) {
    asm volatile("mbarrier.init.shared.b64 [%0], %1;" :: "r"(mbar), "r"(cnt) : "memory");
}
static __device__ __forceinline__ void mbar_expect_tx(uint32_t mbar, uint32_t bytes) {
    asm volatile("mbarrier.arrive.expect_tx.shared.b64 _, [%0], %1;"
                 :: "r"(mbar), "r"(bytes) : "memory");
}
static __device__ __forceinline__ void mbar_wait(uint32_t mbar, uint32_t parity) {
    asm volatile(
        "{\n\t"
        ".reg .pred P;\n\t"
        "WAIT_%=:\n\t"
        "mbarrier.try_wait.parity.acquire.cta.shared::cta.b64 P, [%0], %1, 0x989680;\n\t"
        "@P bra.uni DONE_%=;\n\t"
        "bra.uni WAIT_%=;\n\t"
        "DONE_%=:\n\t"
        "}" :: "r"(mbar), "r"(parity) : "memory");
}
static __device__ __forceinline__ uint64_t make_evict_last_policy() {
    uint64_t pol;
    asm("createpolicy.fractional.L2::evict_last.b64 %0, 1.0;" : "=l"(pol));
    return pol;
}
static __device__ __forceinline__ void bulk_g2s(uint32_t dst, const void* src,
                                                uint32_t bytes, uint32_t mbar,
                                                uint64_t pol) {
    asm volatile(
        "cp.async.bulk.shared::cluster.global.mbarrier::complete_tx::bytes.L2::cache_hint "
        "[%0], [%1], %2, [%3], %4;"
        :: "r"(dst), "l"(src), "r"(bytes), "r"(mbar), "l"(pol) : "memory");
}

static __device__ __forceinline__ float block_reduce(float v) {
    #pragma unroll
    for (int off = 16; off > 0; off >>= 1)
        v += __shfl_down_sync(0xFFFFFFFFu, v, off);
    __shared__ float warp_sums[THREADS / 32];
    int lane = threadIdx.x & 31;
    int wid  = threadIdx.x >> 5;
    if (lane == 0) warp_sums[wid] = v;
    __syncthreads();
    if (wid == 0) {
        v = (lane < (THREADS / 32)) ? warp_sums[lane] : 0.0f;
        #pragma unroll
        for (int off = (THREADS / 64); off > 0; off >>= 1)
            v += __shfl_down_sync(0xFFFFFFFFu, v, off);
    }
    return v;  // valid on thread 0
}

static __device__ __forceinline__ float cell_loss(const float* __restrict__ p,
                                                  const float* __restrict__ t) {
    const float INV_S = 1.0f / 7.0f;

    float conf_t = t[4];
    float coord  = (conf_t > 0.0f) ? 1.0f : 0.0f;

    float t_cx = t[0] * INV_S, t_cy = t[1] * INV_S;
    float t_w  = t[2],          t_h  = t[3];
    float t_l  = t_cx - 0.5f * t_w, t_r = t_cx + 0.5f * t_w;
    float t_t  = t_cy - 0.5f * t_h, t_b = t_cy + 0.5f * t_h;
    float area_t = t_w * t_h;

    float iou[2];
    #pragma unroll
    for (int b = 0; b < 2; b++) {
        float cx = p[5*b]   * INV_S;
        float cy = p[5*b+1] * INV_S;
        float w  = p[5*b+2];
        float h  = p[5*b+3];
        float pl = cx - 0.5f * w, pr = cx + 0.5f * w;
        float pt = cy - 0.5f * h, pb = cy + 0.5f * h;
        float iw = fmaxf(fminf(pr, t_r) - fmaxf(pl, t_l), 0.0f);
        float ih = fmaxf(fminf(pb, t_b) - fmaxf(pt, t_t), 0.0f);
        float inter = iw * ih;
        iou[b] = __fdividef(inter, w * h + area_t - inter);
    }

    bool  sec     = iou[1] > iou[0];          // argmax, first-index tie-break
    float max_iou = fmaxf(iou[0], iou[1]);

    float rp0 = sec ? p[5] : p[0];
    float rp1 = sec ? p[6] : p[1];
    float rp2 = sec ? p[7] : p[2];
    float rp3 = sec ? p[8] : p[3];
    float rp4 = sec ? p[9] : p[4];
    float rt0 = sec ? t[5] : t[0];
    float rt1 = sec ? t[6] : t[1];
    float rt2 = sec ? t[7] : t[2];
    float rt3 = sec ? t[8] : t[3];

    float d0 = rp0 - rt0;
    float d1 = rp1 - rt1;
    float loss_xy = d0 * d0 + d1 * d1;

    float dw = sqrtf(rp2) - sqrtf(rt2);
    float dh = sqrtf(rp3) - sqrtf(rt3);
    float loss_wh = dw * dw + dh * dh;

    float dob = rp4 - max_iou;
    float loss_obj = dob * dob;

    float loss_cls = 0.0f;
    #pragma unroll
    for (int c = 10; c < 14; c++) {
        float pc = p[c], tc = t[c];
        loss_cls -= tc * __logf(pc) + (1.0f - tc) * __logf(1.0f - pc);
    }

    float s = coord * (loss_xy + loss_wh + loss_obj + loss_cls);

    float q  = conf_t;
    float pp = p[4];
    float alpha = __fdividef(1.0f - q, 1.0f - pp);
    s += alpha * (pp - q) * __logf(pp) + (q - pp) * __logf(1.0f - pp);
    return s;
}

// tid 0 issues the bulk copies for stage `st` into ring buffer `b`.
static __device__ __forceinline__ void prefetch_stage(
        const char* __restrict__ pred_b, const char* __restrict__ tgt_b,
        uint32_t sh_u32, int b, long long st, int nstages, uint64_t pol) {
    if (st >= nstages) return;
    if (threadIdx.x == 0) {
        uint32_t mb  = sh_u32 + (uint32_t)b * 8;
        uint32_t dst = sh_u32 + SMEM_DATA_OFF + (uint32_t)b * STG_BYTES;
        mbar_expect_tx(mb, STG_BYTES);
        bulk_g2s(dst,           pred_b + (size_t)st * STG_ONE, STG_ONE, mb, pol);
        bulk_g2s(dst + STG_ONE, tgt_b  + (size_t)st * STG_ONE, STG_ONE, mb, pol);
    }
}

__global__ __launch_bounds__(THREADS)
void yolo_loss_kernel(const float* __restrict__ pred,
                      const float* __restrict__ tgt,
                      float* __restrict__ out,
                      int cells, int nstages, int nblocks) {
    extern __shared__ char sh[];
    uint32_t sh_u32;
    asm("{ .reg .u64 t; cvta.to.shared.u64 t, %1; cvt.u32.u64 %0, t; }"
        : "=r"(sh_u32) : "l"(sh));

    const char* pred_b = (const char*)pred;
    const char* tgt_b  = (const char*)tgt;
    int tid = threadIdx.x;
    int G   = gridDim.x;
    uint64_t pol = make_evict_last_policy();

    if (tid == 0) {
        #pragma unroll
        for (int b = 0; b < NBUF; b++) mbar_init(sh_u32 + b * 8, 1);
    }
    __syncthreads();

    // Prologue: prefetch my first NBUF-1 stages into buffers 0..2.
    #pragma unroll
    for (int k = 0; k < NBUF - 1; k++)
        prefetch_stage(pred_b, tgt_b, sh_u32, k,
                       (long long)blockIdx.x + (long long)k * G, nstages, pol);

    float sum = 0.0f;
    unsigned int phase_mask = 0;   // bit b = current wait parity of buffer b

    int k = 0;
    for (long long st = blockIdx.x; st < nstages; st += G, k++) {
        int b = k & (NBUF - 1);

        // Wait for stage k in buffer b.
        mbar_wait(sh_u32 + b * 8, (phase_mask >> b) & 1u);
        phase_mask ^= (1u << b);

        // Prefetch stage k+NBUF-1 into buffer (k+NBUF-1)%NBUF (held stage
        // k-1; all threads finished it at the end-of-iteration barrier).
        prefetch_stage(pred_b, tgt_b, sh_u32, (k + NBUF - 1) & (NBUF - 1),
                       st + (long long)(NBUF - 1) * G, nstages, pol);

        long long cell = st * CELLS_PER_STG + tid;
        if (cell < cells) {
            const float* base = (const float*)(sh + SMEM_DATA_OFF + b * STG_BYTES);
            const float* p = base + tid * 14;
            const float* t = base + (STG_ONE / 4) + tid * 14;
            sum += cell_loss(p, t);
        }
        __syncthreads();   // all reads of buffer b done before it is refilled
    }

    float bsum = block_reduce(sum);

    __shared__ bool is_last;
    if (tid == 0) {
        g_partials[blockIdx.x] = bsum;
        __threadfence();
        unsigned int v = atomicAdd(&g_count, 1u);
        is_last = (v == (unsigned int)(nblocks - 1));
    }
    __syncthreads();

    if (is_last) {
        float fs = 0.0f;
        for (int b = tid; b < nblocks; b += THREADS)
            fs += g_partials[b];
        float total = block_reduce(fs);
        if (tid == 0) {
            out[0] = total;
            g_count = 0;  // reset for next graph replay
        }
    }
}

extern "C" void kernel_launch(void* const* d_in, const int* in_sizes, int n_in,
                              void* d_out, int out_size) {
    const float* pred = (const float*)d_in[0];
    const float* tgt  = (const float*)d_in[1];
    float* out = (float*)d_out;

    int cells   = in_sizes[0] / 14;                                   // 802816
    int nstages = (cells + CELLS_PER_STG - 1) / CELLS_PER_STG;        // 6272

    int blocks = 592;                        // 4 CTAs/SM x 148 SMs
    if (blocks > nstages) blocks = nstages;
    if (blocks > MAX_BLOCKS) blocks = MAX_BLOCKS;

    static bool attr_set = false;
    if (!attr_set) {
        cudaFuncSetAttribute(yolo_loss_kernel,
                             cudaFuncAttributeMaxDynamicSharedMemorySize,
                             SMEM_BYTES);
        attr_set = true;
    }

    yolo_loss_kernel<<<blocks, THREADS, SMEM_BYTES>>>(pred, tgt, out,
                                                      cells, nstages, blocks);
}

// round 14
// speedup vs baseline: 1.5204x; 1.5204x over previous
#include <cuda_runtime.h>
#include <cstdint>
#include <math.h>

// YOLO loss over [16384, 7, 7, 14] fp32 (~90 MB read, scalar out).
// R14: R12's winning bulk-TMA shape (256 thr, 57 KB smem, 3 CTAs/SM), but
// each CTA is split into TWO independent 128-thread half-pipelines with
// separate 2-buffer TMA rings and named barriers. The halves drift out of
// phase, so one half's TMA fetch overlaps the other half's compute phase,
// closing the lockstep DRAM duty-cycle gap (61% in R12's profile).

#define THREADS        256
#define HALF_THREADS   128
#define CELLS_PER_STG  128                       // per half-stage
#define STG_ONE        7168                      // 128 cells * 56 B
#define STG_BYTES      (2 * STG_ONE)             // 14336 (pred+tgt)
#define SMEM_DATA_OFF  128                       // mbarriers live below
#define SMEM_BYTES     (SMEM_DATA_OFF + 4 * STG_BYTES)   // 57472 B
#define MAX_BLOCKS     8192

__device__ float        g_partials[MAX_BLOCKS];
__device__ unsigned int g_count = 0;

static __device__ __forceinline__ void mbar_init(uint32_t mbar, uint32_t cnt) {
    asm volatile("mbarrier.init.shared.b64 [%0], %1;" :: "r"(mbar), "r"(cnt) : "memory");
}
static __device__ __forceinline__ void mbar_expect_tx(uint32_t mbar, uint32_t bytes) {
    asm volatile("mbarrier.arrive.expect_tx.shared.b64 _, [%0], %1;"
                 :: "r"(mbar), "r"(bytes) : "memory");
}
static __device__ __forceinline__ void mbar_wait(uint32_t mbar, uint32_t parity) {
    asm volatile(
        "{\n\t"
        ".reg .pred P;\n\t"
        "WAIT_%=:\n\t"
        "mbarrier.try_wait.parity.acquire.cta.shared::cta.b64 P, [%0], %1, 0x989680;\n\t"
        "@P bra.uni DONE_%=;\n\t"
        "bra.uni WAIT_%=;\n\t"
        "DONE_%=:\n\t"
        "}" :: "r"(mbar), "r"(parity) : "memory");
}
static __device__ __forceinline__ void named_bar(uint32_t id) {
    asm volatile("bar.sync %0, %1;" :: "r"(id), "r"((uint32_t)HALF_THREADS) : "memory");
}
static __device__ __forceinline__ uint64_t make_evict_last_policy() {
    uint64_t pol;
    asm("createpolicy.fractional.L2::evict_last.b64 %0, 1.0;" : "=l"(pol));
    return pol;
}
static __device__ __forceinline__ void bulk_g2s(uint32_t dst, const void* src,
                                                uint32_t bytes, uint32_t mbar,
                                                uint64_t pol) {
    asm volatile(
        "cp.async.bulk.shared::cluster.global.mbarrier::complete_tx::bytes.L2::cache_hint "
        "[%0], [%1], %2, [%3], %4;"
        :: "r"(dst), "l"(src), "r"(bytes), "r"(mbar), "l"(pol) : "memory");
}

static __device__ __forceinline__ float block_reduce(float v) {
    #pragma unroll
    for (int off = 16; off > 0; off >>= 1)
        v += __shfl_down_sync(0xFFFFFFFFu, v, off);
    __shared__ float warp_sums[THREADS / 32];
    int lane = threadIdx.x & 31;
    int wid  = threadIdx.x >> 5;
    if (lane == 0) warp_sums[wid] = v;
    __syncthreads();
    if (wid == 0) {
        v = (lane < (THREADS / 32)) ? warp_sums[lane] : 0.0f;
        #pragma unroll
        for (int off = (THREADS / 64); off > 0; off >>= 1)
            v += __shfl_down_sync(0xFFFFFFFFu, v, off);
    }
    return v;  // valid on thread 0
}

static __device__ __forceinline__ float cell_loss(const float* __restrict__ p,
                                                  const float* __restrict__ t) {
    const float INV_S = 1.0f / 7.0f;

    float conf_t = t[4];
    float coord  = (conf_t > 0.0f) ? 1.0f : 0.0f;

    float t_cx = t[0] * INV_S, t_cy = t[1] * INV_S;
    float t_w  = t[2],          t_h  = t[3];
    float t_l  = t_cx - 0.5f * t_w, t_r = t_cx + 0.5f * t_w;
    float t_t  = t_cy - 0.5f * t_h, t_b = t_cy + 0.5f * t_h;
    float area_t = t_w * t_h;

    float iou[2];
    #pragma unroll
    for (int b = 0; b < 2; b++) {
        float cx = p[5*b]   * INV_S;
        float cy = p[5*b+1] * INV_S;
        float w  = p[5*b+2];
        float h  = p[5*b+3];
        float pl = cx - 0.5f * w, pr = cx + 0.5f * w;
        float pt = cy - 0.5f * h, pb = cy + 0.5f * h;
        float iw = fmaxf(fminf(pr, t_r) - fmaxf(pl, t_l), 0.0f);
        float ih = fmaxf(fminf(pb, t_b) - fmaxf(pt, t_t), 0.0f);
        float inter = iw * ih;
        iou[b] = __fdividef(inter, w * h + area_t - inter);
    }

    bool  sec     = iou[1] > iou[0];          // argmax, first-index tie-break
    float max_iou = fmaxf(iou[0], iou[1]);

    float rp0 = sec ? p[5] : p[0];
    float rp1 = sec ? p[6] : p[1];
    float rp2 = sec ? p[7] : p[2];
    float rp3 = sec ? p[8] : p[3];
    float rp4 = sec ? p[9] : p[4];
    float rt0 = sec ? t[5] : t[0];
    float rt1 = sec ? t[6] : t[1];
    float rt2 = sec ? t[7] : t[2];
    float rt3 = sec ? t[8] : t[3];

    float d0 = rp0 - rt0;
    float d1 = rp1 - rt1;
    float loss_xy = d0 * d0 + d1 * d1;

    float dw = sqrtf(rp2) - sqrtf(rt2);
    float dh = sqrtf(rp3) - sqrtf(rt3);
    float loss_wh = dw * dw + dh * dh;

    float dob = rp4 - max_iou;
    float loss_obj = dob * dob;

    float loss_cls = 0.0f;
    #pragma unroll
    for (int c = 10; c < 14; c++) {
        float pc = p[c], tc = t[c];
        loss_cls -= tc * __logf(pc) + (1.0f - tc) * __logf(1.0f - pc);
    }

    float s = coord * (loss_xy + loss_wh + loss_obj + loss_cls);

    float q  = conf_t;
    float pp = p[4];
    float alpha = __fdividef(1.0f - q, 1.0f - pp);
    s += alpha * (pp - q) * __logf(pp) + (q - pp) * __logf(1.0f - pp);
    return s;
}

__global__ __launch_bounds__(THREADS)
void yolo_loss_kernel(const float* __restrict__ pred,
                      const float* __restrict__ tgt,
                      float* __restrict__ out,
                      int cells, int nstages, int nblocks) {
    extern __shared__ char sh[];
    uint32_t sh_u32;
    asm("{ .reg .u64 t; cvta.to.shared.u64 t, %1; cvt.u32.u64 %0, t; }"
        : "=r"(sh_u32) : "l"(sh));

    const char* pred_b = (const char*)pred;
    const char* tgt_b  = (const char*)tgt;
    int tid  = threadIdx.x;
    int h    = tid >> 7;             // half id: 0 or 1
    int ltid = tid & (HALF_THREADS - 1);
    uint64_t pol = make_evict_last_policy();

    if (tid == 0) {
        #pragma unroll
        for (int j = 0; j < 4; j++) mbar_init(sh_u32 + j * 8, 1);
    }
    __syncthreads();

    // This half's substream: stages h0 = 2*blockIdx.x + h, step 2*G.
    long long G2  = 2LL * gridDim.x;
    long long st0 = 2LL * blockIdx.x + h;
    uint32_t  jbase = (uint32_t)h * 2;   // buffers {jbase, jbase+1}

    // Prologue: prefetch stage k=0 into buffer jbase.
    if (ltid == 0 && st0 < nstages) {
        uint32_t mb  = sh_u32 + jbase * 8;
        uint32_t dst = sh_u32 + SMEM_DATA_OFF + jbase * STG_BYTES;
        mbar_expect_tx(mb, STG_BYTES);
        bulk_g2s(dst,           pred_b + (size_t)st0 * STG_ONE, STG_ONE, mb, pol);
        bulk_g2s(dst + STG_ONE, tgt_b  + (size_t)st0 * STG_ONE, STG_ONE, mb, pol);
    }

    float sum = 0.0f;
    unsigned int phase = 0;   // bit b = wait parity for buffer jbase+b

    int k = 0;
    for (long long st = st0; st < nstages; st += G2, k++) {
        int b = k & 1;
        uint32_t j = jbase + (uint32_t)b;

        // Prefetch next stage into other buffer (holds stage k-1, consumed
        // before the named barrier at the end of the previous iteration).
        long long nst = st + G2;
        if (ltid == 0 && nst < nstages) {
            uint32_t j2  = jbase + (uint32_t)(b ^ 1);
            uint32_t mb2 = sh_u32 + j2 * 8;
            uint32_t d2  = sh_u32 + SMEM_DATA_OFF + j2 * STG_BYTES;
            mbar_expect_tx(mb2, STG_BYTES);
            bulk_g2s(d2,           pred_b + (size_t)nst * STG_ONE, STG_ONE, mb2, pol);
            bulk_g2s(d2 + STG_ONE, tgt_b  + (size_t)nst * STG_ONE, STG_ONE, mb2, pol);
        }

        // Wait for this stage's bulk copies.
        mbar_wait(sh_u32 + j * 8, (phase >> b) & 1u);
        phase ^= (1u << b);

        long long cell = st * CELLS_PER_STG + ltid;
        if (cell < cells) {
            const float* base = (const float*)(sh + SMEM_DATA_OFF + j * STG_BYTES);
            const float* p = base + ltid * 14;
            const float* t = base + (STG_ONE / 4) + ltid * 14;
            sum += cell_loss(p, t);
        }
        named_bar(h + 1);    // this half done with buffer j
    }

    float bsum = block_reduce(sum);

    __shared__ bool is_last;
    if (tid == 0) {
        g_partials[blockIdx.x] = bsum;
        __threadfence();
        unsigned int v = atomicAdd(&g_count, 1u);
        is_last = (v == (unsigned int)(nblocks - 1));
    }
    __syncthreads();

    if (is_last) {
        float fs = 0.0f;
        for (int b = tid; b < nblocks; b += THREADS)
            fs += g_partials[b];
        float total = block_reduce(fs);
        if (tid == 0) {
            out[0] = total;
            g_count = 0;  // reset for next graph replay
        }
    }
}

extern "C" void kernel_launch(void* const* d_in, const int* in_sizes, int n_in,
                              void* d_out, int out_size) {
    const float* pred = (const float*)d_in[0];
    const float* tgt  = (const float*)d_in[1];
    float* out = (float*)d_out;

    int cells   = in_sizes[0] / 14;                                   // 802816
    int nstages = (cells + CELLS_PER_STG - 1) / CELLS_PER_STG;        // 6272

    int blocks = 448;         // 896 substreams x exactly 7 stages each
    if (blocks > MAX_BLOCKS) blocks = MAX_BLOCKS;

    static bool attr_set = false;
    if (!attr_set) {
        cudaFuncSetAttribute(yolo_loss_kernel,
                             cudaFuncAttributeMaxDynamicSharedMemorySize,
                             SMEM_BYTES);
        attr_set = true;
    }

    yolo_loss_kernel<<<blocks, THREADS, SMEM_BYTES>>>(pred, tgt, out,
                                                      cells, nstages, blocks);
}

// round 15
// speedup vs baseline: 1.5237x; 1.0022x over previous
#include <cuda_runtime.h>
#include <cstdint>
#include <math.h>

// YOLO loss over [16384, 7, 7, 14] fp32 (~90 MB read, scalar out).
// R15: bulk-TMA double-buffered pipeline (R11/R12 WIN) with 224-cell stages
// (802816/224 = 3584 exactly): 50.3 KB smem -> 4 CTAs/SM (vs 3), grid 592.
// More warps/SM + 4 independent TMA streams per SM to fill DRAM duty gaps.

#define THREADS        256
#define CELLS_PER_STG  224
#define STG_ONE        12544                     // 224 cells * 56 B
#define STG_BYTES      (2 * STG_ONE)             // 25088 (pred+tgt)
#define SMEM_DATA_OFF  128                       // mbarriers live below
#define SMEM_BYTES     (SMEM_DATA_OFF + 2 * STG_BYTES)   // 50304 B
#define MAX_BLOCKS     8192

__device__ float        g_partials[MAX_BLOCKS];
__device__ unsigned int g_count = 0;

static __device__ __forceinline__ void mbar_init(uint32_t mbar, uint32_t cnt) {
    asm volatile("mbarrier.init.shared.b64 [%0], %1;" :: "r"(mbar), "r"(cnt) : "memory");
}
static __device__ __forceinline__ void mbar_expect_tx(uint32_t mbar, uint32_t bytes) {
    asm volatile("mbarrier.arrive.expect_tx.shared.b64 _, [%0], %1;"
                 :: "r"(mbar), "r"(bytes) : "memory");
}
static __device__ __forceinline__ void mbar_wait(uint32_t mbar, uint32_t parity) {
    asm volatile(
        "{\n\t"
        ".reg .pred P;\n\t"
        "WAIT_%=:\n\t"
        "mbarrier.try_wait.parity.acquire.cta.shared::cta.b64 P, [%0], %1, 0x989680;\n\t"
        "@P bra.uni DONE_%=;\n\t"
        "bra.uni WAIT_%=;\n\t"
        "DONE_%=:\n\t"
        "}" :: "r"(mbar), "r"(parity) : "memory");
}
static __device__ __forceinline__ uint64_t make_evict_last_policy() {
    uint64_t pol;
    asm("createpolicy.fractional.L2::evict_last.b64 %0, 1.0;" : "=l"(pol));
    return pol;
}
static __device__ __forceinline__ void bulk_g2s(uint32_t dst, const void* src,
                                                uint32_t bytes, uint32_t mbar,
                                                uint64_t pol) {
    asm volatile(
        "cp.async.bulk.shared::cluster.global.mbarrier::complete_tx::bytes.L2::cache_hint "
        "[%0], [%1], %2, [%3], %4;"
        :: "r"(dst), "l"(src), "r"(bytes), "r"(mbar), "l"(pol) : "memory");
}

static __device__ __forceinline__ float block_reduce(float v) {
    #pragma unroll
    for (int off = 16; off > 0; off >>= 1)
        v += __shfl_down_sync(0xFFFFFFFFu, v, off);
    __shared__ float warp_sums[THREADS / 32];
    int lane = threadIdx.x & 31;
    int wid  = threadIdx.x >> 5;
    if (lane == 0) warp_sums[wid] = v;
    __syncthreads();
    if (wid == 0) {
        v = (lane < (THREADS / 32)) ? warp_sums[lane] : 0.0f;
        #pragma unroll
        for (int off = (THREADS / 64); off > 0; off >>= 1)
            v += __shfl_down_sync(0xFFFFFFFFu, v, off);
    }
    return v;  // valid on thread 0
}

static __device__ __forceinline__ float cell_loss(const float* __restrict__ p,
                                                  const float* __restrict__ t) {
    const float INV_S = 1.0f / 7.0f;

    float conf_t = t[4];
    float coord  = (conf_t > 0.0f) ? 1.0f : 0.0f;

    float t_cx = t[0] * INV_S, t_cy = t[1] * INV_S;
    float t_w  = t[2],          t_h  = t[3];
    float t_l  = t_cx - 0.5f * t_w, t_r = t_cx + 0.5f * t_w;
    float t_t  = t_cy - 0.5f * t_h, t_b = t_cy + 0.5f * t_h;
    float area_t = t_w * t_h;

    float iou[2];
    #pragma unroll
    for (int b = 0; b < 2; b++) {
        float cx = p[5*b]   * INV_S;
        float cy = p[5*b+1] * INV_S;
        float w  = p[5*b+2];
        float h  = p[5*b+3];
        float pl = cx - 0.5f * w, pr = cx + 0.5f * w;
        float pt = cy - 0.5f * h, pb = cy + 0.5f * h;
        float iw = fmaxf(fminf(pr, t_r) - fmaxf(pl, t_l), 0.0f);
        float ih = fmaxf(fminf(pb, t_b) - fmaxf(pt, t_t), 0.0f);
        float inter = iw * ih;
        iou[b] = __fdividef(inter, w * h + area_t - inter);
    }

    bool  sec     = iou[1] > iou[0];          // argmax, first-index tie-break
    float max_iou = fmaxf(iou[0], iou[1]);

    float rp0 = sec ? p[5] : p[0];
    float rp1 = sec ? p[6] : p[1];
    float rp2 = sec ? p[7] : p[2];
    float rp3 = sec ? p[8] : p[3];
    float rp4 = sec ? p[9] : p[4];
    float rt0 = sec ? t[5] : t[0];
    float rt1 = sec ? t[6] : t[1];
    float rt2 = sec ? t[7] : t[2];
    float rt3 = sec ? t[8] : t[3];

    float d0 = rp0 - rt0;
    float d1 = rp1 - rt1;
    float loss_xy = d0 * d0 + d1 * d1;

    float dw = sqrtf(rp2) - sqrtf(rt2);
    float dh = sqrtf(rp3) - sqrtf(rt3);
    float loss_wh = dw * dw + dh * dh;

    float dob = rp4 - max_iou;
    float loss_obj = dob * dob;

    float loss_cls = 0.0f;
    #pragma unroll
    for (int c = 10; c < 14; c++) {
        float pc = p[c], tc = t[c];
        loss_cls -= tc * __logf(pc) + (1.0f - tc) * __logf(1.0f - pc);
    }

    float s = coord * (loss_xy + loss_wh + loss_obj + loss_cls);

    float q  = conf_t;
    float pp = p[4];
    float alpha = __fdividef(1.0f - q, 1.0f - pp);
    s += alpha * (pp - q) * __logf(pp) + (q - pp) * __logf(1.0f - pp);
    return s;
}

// tid 0 issues the bulk copies for stage `st` into buffer `b`.
static __device__ __forceinline__ void prefetch_stage(
        const char* __restrict__ pred_b, const char* __restrict__ tgt_b,
        uint32_t sh_u32, int b, long long st, int nstages, uint64_t pol) {
    if (st >= nstages) return;
    if (threadIdx.x == 0) {
        uint32_t mb  = sh_u32 + (uint32_t)b * 8;
        uint32_t dst = sh_u32 + SMEM_DATA_OFF + (uint32_t)b * STG_BYTES;
        mbar_expect_tx(mb, STG_BYTES);
        bulk_g2s(dst,           pred_b + (size_t)st * STG_ONE, STG_ONE, mb, pol);
        bulk_g2s(dst + STG_ONE, tgt_b  + (size_t)st * STG_ONE, STG_ONE, mb, pol);
    }
}

__global__ __launch_bounds__(THREADS)
void yolo_loss_kernel(const float* __restrict__ pred,
                      const float* __restrict__ tgt,
                      float* __restrict__ out,
                      int cells, int nstages, int nblocks) {
    extern __shared__ char sh[];
    uint32_t sh_u32;
    asm("{ .reg .u64 t; cvta.to.shared.u64 t, %1; cvt.u32.u64 %0, t; }"
        : "=r"(sh_u32) : "l"(sh));

    const char* pred_b = (const char*)pred;
    const char* tgt_b  = (const char*)tgt;
    int tid = threadIdx.x;
    int G   = gridDim.x;
    uint64_t pol = make_evict_last_policy();

    if (tid == 0) {
        mbar_init(sh_u32,     1);
        mbar_init(sh_u32 + 8, 1);
    }
    __syncthreads();

    float sum = 0.0f;
    int ph0 = 0, ph1 = 0;
    int idx = 0;

    prefetch_stage(pred_b, tgt_b, sh_u32, 0, blockIdx.x, nstages, pol);

    for (long long st = blockIdx.x; st < nstages; st += G) {
        // Prefetch next stage into the other buffer (free since st-G's
        // consumers passed the __syncthreads at the end of that iteration).
        prefetch_stage(pred_b, tgt_b, sh_u32, idx ^ 1, st + G, nstages, pol);

        // Wait for current stage's bulk copies.
        if (idx == 0) { mbar_wait(sh_u32,     ph0); ph0 ^= 1; }
        else          { mbar_wait(sh_u32 + 8, ph1); ph1 ^= 1; }

        long long cell = st * CELLS_PER_STG + tid;
        if (tid < CELLS_PER_STG && cell < cells) {
            const float* base = (const float*)(sh + SMEM_DATA_OFF + idx * STG_BYTES);
            const float* p = base + tid * 14;
            const float* t = base + (STG_ONE / 4) + tid * 14;
            sum += cell_loss(p, t);
        }
        __syncthreads();   // all reads done before this buffer is refilled
        idx ^= 1;
    }

    float bsum = block_reduce(sum);

    __shared__ bool is_last;
    if (tid == 0) {
        g_partials[blockIdx.x] = bsum;
        __threadfence();
        unsigned int v = atomicAdd(&g_count, 1u);
        is_last = (v == (unsigned int)(nblocks - 1));
    }
    __syncthreads();

    if (is_last) {
        float fs = 0.0f;
        for (int b = tid; b < nblocks; b += THREADS)
            fs += g_partials[b];
        float total = block_reduce(fs);
        if (tid == 0) {
            out[0] = total;
            g_count = 0;  // reset for next graph replay
        }
    }
}

extern "C" void kernel_launch(void* const* d_in, const int* in_sizes, int n_in,
                              void* d_out, int out_size) {
    const float* pred = (const float*)d_in[0];
    const float* tgt  = (const float*)d_in[1];
    float* out = (float*)d_out;

    int cells   = in_sizes[0] / 14;                                   // 802816
    int nstages = (cells + CELLS_PER_STG - 1) / CELLS_PER_STG;        // 3584

    int blocks = 592;                        // 4 CTAs/SM x 148 SMs
    if (blocks > nstages) blocks = nstages;
    if (blocks > MAX_BLOCKS) blocks = MAX_BLOCKS;

    static bool attr_set = false;
    if (!attr_set) {
        cudaFuncSetAttribute(yolo_loss_kernel,
                             cudaFuncAttributeMaxDynamicSharedMemorySize,
                             SMEM_BYTES);
        attr_set = true;
    }

    yolo_loss_kernel<<<blocks, THREADS, SMEM_BYTES>>>(pred, tgt, out,
                                                      cells, nstages, blocks);
}